// round 1
// baseline (speedup 1.0000x reference)
#include <cuda_runtime.h>
#include <cstdint>

// Problem shape (fixed for this dataset entry)
#define BB 8
#define NN 256
#define DD 128
#define KK 256   // 2*D

// Scratch: Pi (with b1 folded in) and Pj projections, [B, N, 2D] each.
__device__ float g_Pi[BB * NN * KK];
__device__ float g_Pj[BB * NN * KK];

// ---------------------------------------------------------------------------
// f32x2 packed helpers (full-rate fp32 FMA path on sm_103a)
// ---------------------------------------------------------------------------
__device__ __forceinline__ unsigned long long pack2(float x, float y) {
    unsigned long long r;
    asm("mov.b64 %0, {%1, %2};" : "=l"(r) : "f"(x), "f"(y));
    return r;
}
__device__ __forceinline__ void unpack2(unsigned long long v, float& x, float& y) {
    asm("mov.b64 {%0, %1}, %2;" : "=f"(x), "=f"(y) : "l"(v));
}
__device__ __forceinline__ unsigned long long fma2(unsigned long long a,
                                                   unsigned long long b,
                                                   unsigned long long c) {
    unsigned long long d;
    asm("fma.rn.f32x2 %0, %1, %2, %3;" : "=l"(d) : "l"(a), "l"(b), "l"(c));
    return d;
}

// ---------------------------------------------------------------------------
// Tour output: improved_tour[b, n] = n (as float, exact for 0..255)
// ---------------------------------------------------------------------------
__global__ void tour_kernel(float* __restrict__ out) {
    int idx = blockIdx.x * 256 + threadIdx.x;
    if (idx < BB * NN) out[idx] = (float)(idx & (NN - 1));
}

// ---------------------------------------------------------------------------
// Projection kernel:
//   Pi[b,n,:] = x[b,n]@W1a + x[b,n+1]@W1b + b1   (b1 folded here)
//   Pj[b,n,:] = x[b,n]@W1c + x[b,n+1]@W1d
// One block handles 8 consecutive n for one b; W1 columns read once per block.
// ---------------------------------------------------------------------------
__global__ __launch_bounds__(256) void proj_kernel(const float* __restrict__ x,
                                                   const float* __restrict__ W1,
                                                   const float* __restrict__ b1) {
    int blk = blockIdx.x;           // 0..255
    int b   = blk >> 5;             // /32
    int n0  = (blk & 31) * 8;

    __shared__ float xs[9][DD];     // rows n0..n0+8 (row r+1 is x_next of row r)
    for (int t = threadIdx.x; t < 9 * DD; t += 256) {
        int r = t / DD, d = t % DD;
        int n = (n0 + r) & (NN - 1);
        xs[r][d] = x[((size_t)b * NN + n) * DD + d];
    }
    __syncthreads();

    int c = threadIdx.x;            // output channel 0..255
    float accPi[8], accPj[8];
#pragma unroll
    for (int r = 0; r < 8; r++) { accPi[r] = 0.f; accPj[r] = 0.f; }

#pragma unroll 4
    for (int d = 0; d < DD; d++) {
        float wa = W1[(0 * DD + d) * KK + c];
        float wb = W1[(1 * DD + d) * KK + c];
        float wc = W1[(2 * DD + d) * KK + c];
        float wd = W1[(3 * DD + d) * KK + c];
#pragma unroll
        for (int r = 0; r < 8; r++) {
            float xv  = xs[r][d];
            float xnv = xs[r + 1][d];
            accPi[r] += xv * wa + xnv * wb;
            accPj[r] += xv * wc + xnv * wd;
        }
    }
    float b1c = b1[c];
#pragma unroll
    for (int r = 0; r < 8; r++) {
        int n = n0 + r;
        size_t off = ((size_t)b * NN + n) * KK + c;
        g_Pi[off] = accPi[r] + b1c;
        g_Pj[off] = accPj[r];
    }
}

// ---------------------------------------------------------------------------
// Main pair kernel. Block = (b, i, j-tile of 128).
//   C[j, c] = sum_k relu(Pi[b,i,k] + Pj[b,j,k]) * W2[k, c]       (128x128x256)
//   score[j] = tanh( sum_c relu(C[j,c] + b2[c]) * W3[c] + b3 )
// 256 threads, 8x8 micro-tile per thread, f32x2 packed FMA accumulators.
// ---------------------------------------------------------------------------
#define KT 16

__global__ __launch_bounds__(256, 2) void pair_kernel(const float* __restrict__ W2,
                                                      const float* __restrict__ b2,
                                                      const float* __restrict__ W3,
                                                      const float* __restrict__ b3p,
                                                      float* __restrict__ outm) {
    int bid = blockIdx.x;
    int jt = bid & 1;
    int i  = (bid >> 1) & (NN - 1);
    int b  = bid >> 9;
    int j0 = jt * 128;

    // Tile fully masked (no j >= i+2 inside) -> output stays 0 from memset.
    if (i > j0 + 125) return;

    __shared__ float Pis[KK];
    __shared__ float As[KT][132];   // padded stride to dodge STS bank conflicts
    __shared__ float Bs[KT][128];
    __shared__ float b2s[DD];
    __shared__ float w3s[DD];

    int tid = threadIdx.x;
    int tx = tid & 15;              // col group
    int ty = tid >> 4;              // row group

    // Prologue loads
    Pis[tid] = g_Pi[((size_t)b * NN + i) * KK + tid];
    if (tid < DD) { b2s[tid] = b2[tid]; w3s[tid] = W3[tid]; }
    __syncthreads();

    unsigned long long acc[8][4];
#pragma unroll
    for (int r = 0; r < 8; r++)
#pragma unroll
        for (int q = 0; q < 4; q++) acc[r][q] = 0ull;

    const float* Pjb = &g_Pj[(size_t)(b * NN + j0) * KK];

    for (int kc = 0; kc < KK / KT; kc++) {
        int k0 = kc * KT;
        // Load A chunk: As[k][j] = relu(Pi[k0+k] + Pj[j0+j][k0+k]); transpose on the fly.
#pragma unroll
        for (int q = tid; q < 512; q += 256) {
            int j  = q >> 2;
            int kq = (q & 3) * 4;
            float4 pv = *(const float4*)&Pjb[(size_t)j * KK + k0 + kq];
            As[kq + 0][j] = fmaxf(pv.x + Pis[k0 + kq + 0], 0.f);
            As[kq + 1][j] = fmaxf(pv.y + Pis[k0 + kq + 1], 0.f);
            As[kq + 2][j] = fmaxf(pv.z + Pis[k0 + kq + 2], 0.f);
            As[kq + 3][j] = fmaxf(pv.w + Pis[k0 + kq + 3], 0.f);
        }
        // Load B chunk: W2[k0+k][c], already row-major contiguous.
#pragma unroll
        for (int q = tid; q < 512; q += 256) {
            int k  = q >> 5;
            int cq = (q & 31) * 4;
            *(float4*)&Bs[k][cq] = *(const float4*)&W2[(size_t)(k0 + k) * DD + cq];
        }
        __syncthreads();

#pragma unroll
        for (int kk = 0; kk < KT; kk++) {
            float4 a0  = *(const float4*)&As[kk][ty * 4];
            float4 a1  = *(const float4*)&As[kk][64 + ty * 4];
            float4 bv0 = *(const float4*)&Bs[kk][tx * 4];
            float4 bv1 = *(const float4*)&Bs[kk][64 + tx * 4];
            unsigned long long p0 = pack2(bv0.x, bv0.y);
            unsigned long long p1 = pack2(bv0.z, bv0.w);
            unsigned long long p2 = pack2(bv1.x, bv1.y);
            unsigned long long p3 = pack2(bv1.z, bv1.w);
            float ar[8] = {a0.x, a0.y, a0.z, a0.w, a1.x, a1.y, a1.z, a1.w};
#pragma unroll
            for (int r = 0; r < 8; r++) {
                unsigned long long aa = pack2(ar[r], ar[r]);
                acc[r][0] = fma2(aa, p0, acc[r][0]);
                acc[r][1] = fma2(aa, p1, acc[r][1]);
                acc[r][2] = fma2(aa, p2, acc[r][2]);
                acc[r][3] = fma2(aa, p3, acc[r][3]);
            }
        }
        __syncthreads();
    }

    // Epilogue: h2 = relu(C + b2); score = tanh(h2 . W3 + b3); mask; store.
    float b3v = b3p[0];
    int cbase0 = tx * 4;
    int cbase1 = 64 + tx * 4;
    float b2v[8], w3v[8];
#pragma unroll
    for (int s = 0; s < 4; s++) {
        b2v[s]     = b2s[cbase0 + s];  w3v[s]     = w3s[cbase0 + s];
        b2v[4 + s] = b2s[cbase1 + s];  w3v[4 + s] = w3s[cbase1 + s];
    }

#pragma unroll
    for (int r = 0; r < 8; r++) {
        int rowIdx = (r < 4) ? (ty * 4 + r) : (64 + ty * 4 + (r - 4));
        float sum = 0.f;
#pragma unroll
        for (int q = 0; q < 4; q++) {
            float v0, v1;
            unpack2(acc[r][q], v0, v1);
            int s0 = q * 2, s1 = q * 2 + 1;
            sum += fmaxf(v0 + b2v[s0], 0.f) * w3v[s0];
            sum += fmaxf(v1 + b2v[s1], 0.f) * w3v[s1];
        }
        // Reduce over the 16 tx lanes (stays inside each 16-lane half of the warp)
#pragma unroll
        for (int off = 8; off >= 1; off >>= 1)
            sum += __shfl_xor_sync(0xffffffffu, sum, off);

        if (tx == 0) {
            int j = j0 + rowIdx;
            bool valid = (j >= i + 2) && ((j - i) != (NN - 1));
            float score = tanhf(sum + b3v);
            outm[((size_t)(b * NN + i)) * NN + j] = valid ? score : 0.f;
        }
    }
}

// ---------------------------------------------------------------------------
// Launcher
// ---------------------------------------------------------------------------
extern "C" void kernel_launch(void* const* d_in, const int* in_sizes, int n_in,
                              void* d_out, int out_size) {
    const float* x  = (const float*)d_in[0];
    const float* W1 = (const float*)d_in[1];
    const float* b1 = (const float*)d_in[2];
    const float* W2 = (const float*)d_in[3];
    const float* b2 = (const float*)d_in[4];
    const float* W3 = (const float*)d_in[5];
    const float* b3 = (const float*)d_in[6];
    float* out = (float*)d_out;

    const int MAT  = BB * NN * NN;   // 524288
    const int TOUR = BB * NN;        // 2048

    size_t matOff = 0;
    bool hasTour = false;
    if (out_size >= MAT + TOUR) { hasTour = true; matOff = (size_t)out_size - MAT; }
    // else: matrix-only layout, matOff = 0

    // Zero everything: masked pairs and skipped tiles must read 0.
    cudaMemsetAsync(d_out, 0, (size_t)out_size * sizeof(float), 0);

    if (hasTour) tour_kernel<<<(TOUR + 255) / 256, 256>>>(out);

    proj_kernel<<<256, 256>>>(x, W1, b1);
    pair_kernel<<<BB * NN * 2, 256>>>(W2, b2, W3, b3, out + matOff);
}

// round 2
// speedup vs baseline: 1.0012x; 1.0012x over previous
#include <cuda_runtime.h>
#include <cstdint>

// Problem shape (fixed for this dataset entry)
#define BB 8
#define NN 256
#define DD 128
#define KK 256   // 2*D

// Scratch: Pi (with b1 folded in) and Pj projections, [B, N, 2D] each.
__device__ float g_Pi[BB * NN * KK];
__device__ float g_Pj[BB * NN * KK];

// ---------------------------------------------------------------------------
// f32x2 packed helpers (full-rate fp32 FMA path on sm_103a)
// ---------------------------------------------------------------------------
__device__ __forceinline__ unsigned long long pack2(float x, float y) {
    unsigned long long r;
    asm("mov.b64 %0, {%1, %2};" : "=l"(r) : "f"(x), "f"(y));
    return r;
}
__device__ __forceinline__ void unpack2(unsigned long long v, float& x, float& y) {
    asm("mov.b64 {%0, %1}, %2;" : "=f"(x), "=f"(y) : "l"(v));
}
__device__ __forceinline__ unsigned long long fma2(unsigned long long a,
                                                   unsigned long long b,
                                                   unsigned long long c) {
    unsigned long long d;
    asm("fma.rn.f32x2 %0, %1, %2, %3;" : "=l"(d) : "l"(a), "l"(b), "l"(c));
    return d;
}

// ---------------------------------------------------------------------------
// Tour output: improved_tour[b, n] = n (as float, exact for 0..255)
// ---------------------------------------------------------------------------
__global__ void tour_kernel(float* __restrict__ out) {
    int idx = blockIdx.x * 256 + threadIdx.x;
    if (idx < BB * NN) out[idx] = (float)(idx & (NN - 1));
}

// ---------------------------------------------------------------------------
// Projection kernel:
//   Pi[b,n,:] = x[b,n]@W1a + x[b,n+1]@W1b + b1   (b1 folded here)
//   Pj[b,n,:] = x[b,n]@W1c + x[b,n+1]@W1d
// One block handles 8 consecutive n for one b; W1 columns read once per block.
// ---------------------------------------------------------------------------
__global__ __launch_bounds__(256) void proj_kernel(const float* __restrict__ x,
                                                   const float* __restrict__ W1,
                                                   const float* __restrict__ b1) {
    int blk = blockIdx.x;           // 0..255
    int b   = blk >> 5;             // /32
    int n0  = (blk & 31) * 8;

    __shared__ float xs[9][DD];     // rows n0..n0+8 (row r+1 is x_next of row r)
    for (int t = threadIdx.x; t < 9 * DD; t += 256) {
        int r = t / DD, d = t % DD;
        int n = (n0 + r) & (NN - 1);
        xs[r][d] = x[((size_t)b * NN + n) * DD + d];
    }
    __syncthreads();

    int c = threadIdx.x;            // output channel 0..255
    float accPi[8], accPj[8];
#pragma unroll
    for (int r = 0; r < 8; r++) { accPi[r] = 0.f; accPj[r] = 0.f; }

#pragma unroll 4
    for (int d = 0; d < DD; d++) {
        float wa = W1[(0 * DD + d) * KK + c];
        float wb = W1[(1 * DD + d) * KK + c];
        float wc = W1[(2 * DD + d) * KK + c];
        float wd = W1[(3 * DD + d) * KK + c];
#pragma unroll
        for (int r = 0; r < 8; r++) {
            float xv  = xs[r][d];
            float xnv = xs[r + 1][d];
            accPi[r] += xv * wa + xnv * wb;
            accPj[r] += xv * wc + xnv * wd;
        }
    }
    float b1c = b1[c];
#pragma unroll
    for (int r = 0; r < 8; r++) {
        int n = n0 + r;
        size_t off = ((size_t)b * NN + n) * KK + c;
        g_Pi[off] = accPi[r] + b1c;
        g_Pj[off] = accPj[r];
    }
}

// ---------------------------------------------------------------------------
// Main pair kernel. Block = (b, i, j-tile of 128).
//   C[j, c] = sum_k relu(Pi[b,i,k] + Pj[b,j,k]) * W2[k, c]       (128x128x256)
//   score[j] = tanh( sum_c relu(C[j,c] + b2[c]) * W3[c] + b3 )
// 256 threads, 8x8 micro-tile per thread, f32x2 packed FMA accumulators.
// ---------------------------------------------------------------------------
#define KT 16

__global__ __launch_bounds__(256, 2) void pair_kernel(const float* __restrict__ W2,
                                                      const float* __restrict__ b2,
                                                      const float* __restrict__ W3,
                                                      const float* __restrict__ b3p,
                                                      float* __restrict__ outm) {
    int bid = blockIdx.x;
    int jt = bid & 1;
    int i  = (bid >> 1) & (NN - 1);
    int b  = bid >> 9;
    int j0 = jt * 128;

    // Tile fully masked (no j >= i+2 inside) -> output stays 0 from memset.
    if (i > j0 + 125) return;

    __shared__ float Pis[KK];
    __shared__ float As[KT][132];   // padded stride to dodge STS bank conflicts
    __shared__ float Bs[KT][128];
    __shared__ float b2s[DD];
    __shared__ float w3s[DD];

    int tid = threadIdx.x;
    int tx = tid & 15;              // col group
    int ty = tid >> 4;              // row group

    // Prologue loads
    Pis[tid] = g_Pi[((size_t)b * NN + i) * KK + tid];
    if (tid < DD) { b2s[tid] = b2[tid]; w3s[tid] = W3[tid]; }
    __syncthreads();

    unsigned long long acc[8][4];
#pragma unroll
    for (int r = 0; r < 8; r++)
#pragma unroll
        for (int q = 0; q < 4; q++) acc[r][q] = 0ull;

    const float* Pjb = &g_Pj[(size_t)(b * NN + j0) * KK];

    for (int kc = 0; kc < KK / KT; kc++) {
        int k0 = kc * KT;
        // Load A chunk: As[k][j] = relu(Pi[k0+k] + Pj[j0+j][k0+k]); transpose on the fly.
#pragma unroll
        for (int q = tid; q < 512; q += 256) {
            int j  = q >> 2;
            int kq = (q & 3) * 4;
            float4 pv = *(const float4*)&Pjb[(size_t)j * KK + k0 + kq];
            As[kq + 0][j] = fmaxf(pv.x + Pis[k0 + kq + 0], 0.f);
            As[kq + 1][j] = fmaxf(pv.y + Pis[k0 + kq + 1], 0.f);
            As[kq + 2][j] = fmaxf(pv.z + Pis[k0 + kq + 2], 0.f);
            As[kq + 3][j] = fmaxf(pv.w + Pis[k0 + kq + 3], 0.f);
        }
        // Load B chunk: W2[k0+k][c], already row-major contiguous.
#pragma unroll
        for (int q = tid; q < 512; q += 256) {
            int k  = q >> 5;
            int cq = (q & 31) * 4;
            *(float4*)&Bs[k][cq] = *(const float4*)&W2[(size_t)(k0 + k) * DD + cq];
        }
        __syncthreads();

#pragma unroll
        for (int kk = 0; kk < KT; kk++) {
            float4 a0  = *(const float4*)&As[kk][ty * 4];
            float4 a1  = *(const float4*)&As[kk][64 + ty * 4];
            float4 bv0 = *(const float4*)&Bs[kk][tx * 4];
            float4 bv1 = *(const float4*)&Bs[kk][64 + tx * 4];
            unsigned long long p0 = pack2(bv0.x, bv0.y);
            unsigned long long p1 = pack2(bv0.z, bv0.w);
            unsigned long long p2 = pack2(bv1.x, bv1.y);
            unsigned long long p3 = pack2(bv1.z, bv1.w);
            float ar[8] = {a0.x, a0.y, a0.z, a0.w, a1.x, a1.y, a1.z, a1.w};
#pragma unroll
            for (int r = 0; r < 8; r++) {
                unsigned long long aa = pack2(ar[r], ar[r]);
                acc[r][0] = fma2(aa, p0, acc[r][0]);
                acc[r][1] = fma2(aa, p1, acc[r][1]);
                acc[r][2] = fma2(aa, p2, acc[r][2]);
                acc[r][3] = fma2(aa, p3, acc[r][3]);
            }
        }
        __syncthreads();
    }

    // Epilogue: h2 = relu(C + b2); score = tanh(h2 . W3 + b3); mask; store.
    float b3v = b3p[0];
    int cbase0 = tx * 4;
    int cbase1 = 64 + tx * 4;
    float b2v[8], w3v[8];
#pragma unroll
    for (int s = 0; s < 4; s++) {
        b2v[s]     = b2s[cbase0 + s];  w3v[s]     = w3s[cbase0 + s];
        b2v[4 + s] = b2s[cbase1 + s];  w3v[4 + s] = w3s[cbase1 + s];
    }

#pragma unroll
    for (int r = 0; r < 8; r++) {
        int rowIdx = (r < 4) ? (ty * 4 + r) : (64 + ty * 4 + (r - 4));
        float sum = 0.f;
#pragma unroll
        for (int q = 0; q < 4; q++) {
            float v0, v1;
            unpack2(acc[r][q], v0, v1);
            int s0 = q * 2, s1 = q * 2 + 1;
            sum += fmaxf(v0 + b2v[s0], 0.f) * w3v[s0];
            sum += fmaxf(v1 + b2v[s1], 0.f) * w3v[s1];
        }
        // Reduce over the 16 tx lanes (stays inside each 16-lane half of the warp)
#pragma unroll
        for (int off = 8; off >= 1; off >>= 1)
            sum += __shfl_xor_sync(0xffffffffu, sum, off);

        if (tx == 0) {
            int j = j0 + rowIdx;
            bool valid = (j >= i + 2) && ((j - i) != (NN - 1));
            float score = tanhf(sum + b3v);
            outm[((size_t)(b * NN + i)) * NN + j] = valid ? score : 0.f;
        }
    }
}

// ---------------------------------------------------------------------------
// Launcher
// ---------------------------------------------------------------------------
extern "C" void kernel_launch(void* const* d_in, const int* in_sizes, int n_in,
                              void* d_out, int out_size) {
    const float* x  = (const float*)d_in[0];
    const float* W1 = (const float*)d_in[1];
    const float* b1 = (const float*)d_in[2];
    const float* W2 = (const float*)d_in[3];
    const float* b2 = (const float*)d_in[4];
    const float* W3 = (const float*)d_in[5];
    const float* b3 = (const float*)d_in[6];
    float* out = (float*)d_out;

    const int MAT  = BB * NN * NN;   // 524288
    const int TOUR = BB * NN;        // 2048

    size_t matOff = 0;
    bool hasTour = false;
    if (out_size >= MAT + TOUR) { hasTour = true; matOff = (size_t)out_size - MAT; }
    // else: matrix-only layout, matOff = 0

    // Zero everything: masked pairs and skipped tiles must read 0.
    cudaMemsetAsync(d_out, 0, (size_t)out_size * sizeof(float), 0);

    if (hasTour) tour_kernel<<<(TOUR + 255) / 256, 256>>>(out);

    proj_kernel<<<256, 256>>>(x, W1, b1);
    pair_kernel<<<BB * NN * 2, 256>>>(W2, b2, W3, b3, out + matOff);
}

// round 4
// speedup vs baseline: 2.0234x; 2.0209x over previous
#include <cuda_runtime.h>
#include <cstdint>

// Problem shape (fixed)
#define BB 8
#define NN 256
#define DD 128
#define KK 256   // 2*D

// Scratch: Pi (with b1 folded in) and Pj projections, [B, N, 2D] each.
__device__ float g_Pi[BB * NN * KK];
__device__ float g_Pj[BB * NN * KK];

// ---------------------------------------------------------------------------
// Helpers
// ---------------------------------------------------------------------------
__device__ __forceinline__ float to_tf32(float x) {
    uint32_t u;
    asm("cvt.rna.tf32.f32 %0, %1;" : "=r"(u) : "f"(x));
    return __uint_as_float(u);
}

__device__ __forceinline__ void mma_tf32(float* d,
                                         uint32_t a0, uint32_t a1, uint32_t a2, uint32_t a3,
                                         uint32_t b0, uint32_t b1) {
    asm volatile(
        "mma.sync.aligned.m16n8k8.row.col.f32.tf32.tf32.f32 "
        "{%0,%1,%2,%3}, {%4,%5,%6,%7}, {%8,%9}, {%0,%1,%2,%3};"
        : "+f"(d[0]), "+f"(d[1]), "+f"(d[2]), "+f"(d[3])
        : "r"(a0), "r"(a1), "r"(a2), "r"(a3), "r"(b0), "r"(b1));
}

// ---------------------------------------------------------------------------
// Tour output: improved_tour[b, n] = n
// ---------------------------------------------------------------------------
__global__ void tour_kernel(float* __restrict__ out) {
    int idx = blockIdx.x * 256 + threadIdx.x;
    if (idx < BB * NN) out[idx] = (float)(idx & (NN - 1));
}

// ---------------------------------------------------------------------------
// Projection kernel (fp32 exact):
//   Pi[b,n,:] = x[b,n]@W1a + x[b,n+1]@W1b + b1
//   Pj[b,n,:] = x[b,n]@W1c + x[b,n+1]@W1d
// ---------------------------------------------------------------------------
__global__ __launch_bounds__(256) void proj_kernel(const float* __restrict__ x,
                                                   const float* __restrict__ W1,
                                                   const float* __restrict__ b1) {
    int blk = blockIdx.x;
    int b   = blk >> 5;
    int n0  = (blk & 31) * 8;

    __shared__ float xs[9][DD];
    for (int t = threadIdx.x; t < 9 * DD; t += 256) {
        int r = t / DD, d = t % DD;
        int n = (n0 + r) & (NN - 1);
        xs[r][d] = x[((size_t)b * NN + n) * DD + d];
    }
    __syncthreads();

    int c = threadIdx.x;
    float accPi[8], accPj[8];
#pragma unroll
    for (int r = 0; r < 8; r++) { accPi[r] = 0.f; accPj[r] = 0.f; }

#pragma unroll 4
    for (int d = 0; d < DD; d++) {
        float wa = W1[(0 * DD + d) * KK + c];
        float wb = W1[(1 * DD + d) * KK + c];
        float wc = W1[(2 * DD + d) * KK + c];
        float wd = W1[(3 * DD + d) * KK + c];
#pragma unroll
        for (int r = 0; r < 8; r++) {
            float xv  = xs[r][d];
            float xnv = xs[r + 1][d];
            accPi[r] += xv * wa + xnv * wb;
            accPj[r] += xv * wc + xnv * wd;
        }
    }
    float b1c = b1[c];
#pragma unroll
    for (int r = 0; r < 8; r++) {
        int n = n0 + r;
        size_t off = ((size_t)b * NN + n) * KK + c;
        g_Pi[off] = accPi[r] + b1c;
        g_Pj[off] = accPj[r];
    }
}

// ---------------------------------------------------------------------------
// Pair kernel: CTA = (b, {i0, i0+1}, j-tile of 128). tf32 mma.sync GEMM.
//   For each i: C[j,c] = sum_k relu(Pi[i,k]+Pj[j,k]) * W2[k,c]  (128x128x256)
//   score[i,j] = tanh( sum_c relu(C[j,c]+b2[c]) * W3[c] + b3 )
// 256 threads = 8 warps; warp (wy = wid&3, wx = wid>>2) owns j in
// [wy*32, wy*32+32), c in [wx*64, wx*64+64). K staged in chunks of 16,
// double buffered, one __syncthreads per chunk.
// ---------------------------------------------------------------------------
#define KC  16
#define AST 20     // A smem row stride (floats): 16 + 4 pad -> conflict-free frags
#define BST 136    // B smem row stride (floats): 128 + 8 pad -> conflict-free frags

// smem float offsets
#define OFF_A   0                          // [2 buf][2 i][128][AST] = 10240
#define OFF_B   10240                      // [2 buf][16][BST]       = 4352
#define OFF_PI  14592                      // [2][256]               = 512
#define OFF_B2  15104                      // 128
#define OFF_W3  15232                      // 128
#define OFF_RED 15360                      // [2 i][128 j][2 wx]     = 512
#define SMEM_FLOATS 15872                  // 63488 bytes

__global__ __launch_bounds__(256) void pair_kernel(const float* __restrict__ W2,
                                                   const float* __restrict__ b2g,
                                                   const float* __restrict__ w3g,
                                                   const float* __restrict__ b3g,
                                                   float* __restrict__ outm) {
    extern __shared__ float sm[];
    int tid  = threadIdx.x;
    int lane = tid & 31, wid = tid >> 5;
    int wy = wid & 3, wx = wid >> 2;
    int g  = lane >> 2, tg = lane & 3;

    int bid = blockIdx.x;
    int jt = bid & 1;
    int ig = (bid >> 1) & 127;
    int b  = bid >> 8;
    int j0 = jt << 7, i0 = ig << 1;
    if (i0 > j0 + 125) return;   // fully masked tile (output stays 0 from memset)

    float* As  = sm + OFF_A;
    float* Bs  = sm + OFF_B;
    float* PiS = sm + OFF_PI;
    float* b2s = sm + OFF_B2;
    float* w3s = sm + OFF_W3;
    float* red = sm + OFF_RED;

    const float* Pjb = &g_Pj[(size_t)(b * NN + j0) * KK];

    // Prologue: Pi rows, b2, W3 into smem
    {
        const float* pi0 = &g_Pi[(size_t)(b * NN + i0) * KK];
        PiS[tid]       = pi0[tid];
        PiS[256 + tid] = pi0[KK + tid];
        if (tid < 128) { b2s[tid] = b2g[tid]; w3s[tid] = w3g[tid]; }
    }

    float acc[2][2][8][4];
#pragma unroll
    for (int i = 0; i < 2; i++)
#pragma unroll
        for (int m = 0; m < 2; m++)
#pragma unroll
            for (int n = 0; n < 8; n++)
#pragma unroll
                for (int q = 0; q < 4; q++) acc[i][m][n][q] = 0.f;

    // Prefetch mappings
    int jA  = tid >> 1, kqA = (tid & 1) * 8;     // A: 2 float4 per thread per chunk
    int kB  = tid >> 4, cB  = (tid & 15) * 8;    // B: 2 float4 per thread per chunk

    // Load chunk 0
    float4 pj0 = *(const float4*)&Pjb[(size_t)jA * KK + kqA];
    float4 pj1 = *(const float4*)&Pjb[(size_t)jA * KK + kqA + 4];
    float4 w0  = *(const float4*)&W2[(size_t)kB * DD + cB];
    float4 w1  = *(const float4*)&W2[(size_t)kB * DD + cB + 4];

    __syncthreads();   // PiS ready

    // Store chunk 0 (buf 0)
    {
        int k0 = 0, buf = 0;
#pragma unroll
        for (int i = 0; i < 2; i++) {
            const float* pb = &PiS[i * 256 + k0 + kqA];
            float4 v0, v1;
            v0.x = to_tf32(fmaxf(pj0.x + pb[0], 0.f));
            v0.y = to_tf32(fmaxf(pj0.y + pb[1], 0.f));
            v0.z = to_tf32(fmaxf(pj0.z + pb[2], 0.f));
            v0.w = to_tf32(fmaxf(pj0.w + pb[3], 0.f));
            v1.x = to_tf32(fmaxf(pj1.x + pb[4], 0.f));
            v1.y = to_tf32(fmaxf(pj1.y + pb[5], 0.f));
            v1.z = to_tf32(fmaxf(pj1.z + pb[6], 0.f));
            v1.w = to_tf32(fmaxf(pj1.w + pb[7], 0.f));
            float* ap = &As[((buf * 2 + i) * 128 + jA) * AST + kqA];
            *(float4*)ap = v0;
            *(float4*)(ap + 4) = v1;
        }
        float4 u0, u1;
        u0.x = to_tf32(w0.x); u0.y = to_tf32(w0.y); u0.z = to_tf32(w0.z); u0.w = to_tf32(w0.w);
        u1.x = to_tf32(w1.x); u1.y = to_tf32(w1.y); u1.z = to_tf32(w1.z); u1.w = to_tf32(w1.w);
        float* bp = &Bs[buf * 16 * BST + kB * BST + cB];
        *(float4*)bp = u0;
        *(float4*)(bp + 4) = u1;
    }
    __syncthreads();

    for (int c = 0; c < 16; c++) {
        int buf = c & 1;
        // Prefetch chunk c+1 into registers
        if (c < 15) {
            int k0n = (c + 1) * KC;
            pj0 = *(const float4*)&Pjb[(size_t)jA * KK + k0n + kqA];
            pj1 = *(const float4*)&Pjb[(size_t)jA * KK + k0n + kqA + 4];
            w0  = *(const float4*)&W2[(size_t)(k0n + kB) * DD + cB];
            w1  = *(const float4*)&W2[(size_t)(k0n + kB) * DD + cB + 4];
        }

        // Compute chunk c
        const float* Ab = As + buf * 2 * 128 * AST;
        const float* Bb = Bs + buf * 16 * BST;
#pragma unroll
        for (int ks = 0; ks < 2; ks++) {
            int k = ks * 8;
            uint32_t bf0[8], bf1[8];
#pragma unroll
            for (int n = 0; n < 8; n++) {
                int cc = wx * 64 + n * 8 + g;
                bf0[n] = __float_as_uint(Bb[(k + tg) * BST + cc]);
                bf1[n] = __float_as_uint(Bb[(k + tg + 4) * BST + cc]);
            }
#pragma unroll
            for (int i = 0; i < 2; i++) {
#pragma unroll
                for (int m = 0; m < 2; m++) {
                    int row = wy * 32 + m * 16 + g;
                    const float* ap = Ab + (i * 128 + row) * AST + k + tg;
                    uint32_t a0 = __float_as_uint(ap[0]);
                    uint32_t a1 = __float_as_uint(ap[8 * AST]);
                    uint32_t a2 = __float_as_uint(ap[4]);
                    uint32_t a3 = __float_as_uint(ap[8 * AST + 4]);
#pragma unroll
                    for (int n = 0; n < 8; n++)
                        mma_tf32(acc[i][m][n], a0, a1, a2, a3, bf0[n], bf1[n]);
                }
            }
        }

        // Store chunk c+1 into the other buffer
        if (c < 15) {
            int nb = buf ^ 1;
            int k0n = (c + 1) * KC;
#pragma unroll
            for (int i = 0; i < 2; i++) {
                const float* pb = &PiS[i * 256 + k0n + kqA];
                float4 v0, v1;
                v0.x = to_tf32(fmaxf(pj0.x + pb[0], 0.f));
                v0.y = to_tf32(fmaxf(pj0.y + pb[1], 0.f));
                v0.z = to_tf32(fmaxf(pj0.z + pb[2], 0.f));
                v0.w = to_tf32(fmaxf(pj0.w + pb[3], 0.f));
                v1.x = to_tf32(fmaxf(pj1.x + pb[4], 0.f));
                v1.y = to_tf32(fmaxf(pj1.y + pb[5], 0.f));
                v1.z = to_tf32(fmaxf(pj1.z + pb[6], 0.f));
                v1.w = to_tf32(fmaxf(pj1.w + pb[7], 0.f));
                float* ap = &As[((nb * 2 + i) * 128 + jA) * AST + kqA];
                *(float4*)ap = v0;
                *(float4*)(ap + 4) = v1;
            }
            float4 u0, u1;
            u0.x = to_tf32(w0.x); u0.y = to_tf32(w0.y); u0.z = to_tf32(w0.z); u0.w = to_tf32(w0.w);
            u1.x = to_tf32(w1.x); u1.y = to_tf32(w1.y); u1.z = to_tf32(w1.z); u1.w = to_tf32(w1.w);
            float* bp = &Bs[nb * 16 * BST + kB * BST + cB];
            *(float4*)bp = u0;
            *(float4*)(bp + 4) = u1;
        }
        __syncthreads();
    }

    // Epilogue: per-thread partial dot over its 16 c-columns, shfl + smem reduce
    float b3v = b3g[0];
#pragma unroll
    for (int i = 0; i < 2; i++) {
#pragma unroll
        for (int m = 0; m < 2; m++) {
            float s0 = 0.f, s1 = 0.f;
#pragma unroll
            for (int n = 0; n < 8; n++) {
                int c0 = wx * 64 + n * 8 + tg * 2;
                float bA = b2s[c0],     wA = w3s[c0];
                float bBv = b2s[c0 + 1], wBv = w3s[c0 + 1];
                s0 += fmaxf(acc[i][m][n][0] + bA, 0.f) * wA
                    + fmaxf(acc[i][m][n][1] + bBv, 0.f) * wBv;
                s1 += fmaxf(acc[i][m][n][2] + bA, 0.f) * wA
                    + fmaxf(acc[i][m][n][3] + bBv, 0.f) * wBv;
            }
            s0 += __shfl_xor_sync(0xffffffffu, s0, 1);
            s0 += __shfl_xor_sync(0xffffffffu, s0, 2);
            s1 += __shfl_xor_sync(0xffffffffu, s1, 1);
            s1 += __shfl_xor_sync(0xffffffffu, s1, 2);
            if (tg == 0) {
                int r0 = wy * 32 + m * 16 + g;
                red[(i * 128 + r0) * 2 + wx]     = s0;
                red[(i * 128 + r0 + 8) * 2 + wx] = s1;
            }
        }
    }
    __syncthreads();

    {
        int i  = tid >> 7;
        int jj = tid & 127;
        float sum = red[(i * 128 + jj) * 2] + red[(i * 128 + jj) * 2 + 1] + b3v;
        int iG = i0 + i, j = j0 + jj;
        bool valid = (j >= iG + 2) && ((j - iG) != (NN - 1));
        outm[((size_t)(b * NN + iG)) * NN + j] = valid ? tanhf(sum) : 0.f;
    }
}

// ---------------------------------------------------------------------------
// Launcher
// ---------------------------------------------------------------------------
extern "C" void kernel_launch(void* const* d_in, const int* in_sizes, int n_in,
                              void* d_out, int out_size) {
    const float* x  = (const float*)d_in[0];
    const float* W1 = (const float*)d_in[1];
    const float* b1 = (const float*)d_in[2];
    const float* W2 = (const float*)d_in[3];
    const float* b2 = (const float*)d_in[4];
    const float* W3 = (const float*)d_in[5];
    const float* b3 = (const float*)d_in[6];
    float* out = (float*)d_out;

    const int MAT  = BB * NN * NN;   // 524288
    const int TOUR = BB * NN;        // 2048

    size_t matOff = 0;
    bool hasTour = false;
    if (out_size >= MAT + TOUR) { hasTour = true; matOff = (size_t)out_size - MAT; }

    cudaFuncSetAttribute(pair_kernel, cudaFuncAttributeMaxDynamicSharedMemorySize,
                         SMEM_FLOATS * (int)sizeof(float));

    cudaMemsetAsync(d_out, 0, (size_t)out_size * sizeof(float), 0);
    if (hasTour) tour_kernel<<<(TOUR + 255) / 256, 256>>>(out);

    proj_kernel<<<256, 256>>>(x, W1, b1);
    pair_kernel<<<BB * 128 * 2, 256, SMEM_FLOATS * sizeof(float)>>>(W2, b2, W3, b3,
                                                                    out + matOff);
}

// round 6
// speedup vs baseline: 3.2086x; 1.5858x over previous
#include <cuda_runtime.h>
#include <cuda_fp16.h>
#include <cstdint>

// Problem shape (fixed)
#define BB 8
#define NN 256
#define DD 128
#define KK 256   // 2*D

// Scratch
__device__ float g_Pi[BB * NN * KK];   // Pi with b1 folded in
__device__ float g_Pj[BB * NN * KK];
__device__ __half g_W2h[DD * KK];      // W2 transposed to [c][k], half

// ---------------------------------------------------------------------------
// Helpers
// ---------------------------------------------------------------------------
__device__ __forceinline__ uint32_t h2_as_u32(__half2 h) {
    union { __half2 h; uint32_t u; } cvt;
    cvt.h = h;
    return cvt.u;
}

// fp16 MMA m16n8k16, fp32 accumulate
__device__ __forceinline__ void mma_f16(float* d,
                                        uint32_t a0, uint32_t a1, uint32_t a2, uint32_t a3,
                                        uint32_t b0, uint32_t b1) {
    asm volatile(
        "mma.sync.aligned.m16n8k16.row.col.f32.f16.f16.f32 "
        "{%0,%1,%2,%3}, {%4,%5,%6,%7}, {%8,%9}, {%0,%1,%2,%3};"
        : "+f"(d[0]), "+f"(d[1]), "+f"(d[2]), "+f"(d[3])
        : "r"(a0), "r"(a1), "r"(a2), "r"(a3), "r"(b0), "r"(b1));
}

// ---------------------------------------------------------------------------
// Tour output
// ---------------------------------------------------------------------------
__global__ void tour_kernel(float* __restrict__ out) {
    int idx = blockIdx.x * 256 + threadIdx.x;
    if (idx < BB * NN) out[idx] = (float)(idx & (NN - 1));
}

// ---------------------------------------------------------------------------
// Projection kernel (fp32 exact)
// ---------------------------------------------------------------------------
__global__ __launch_bounds__(256) void proj_kernel(const float* __restrict__ x,
                                                   const float* __restrict__ W1,
                                                   const float* __restrict__ b1) {
    int blk = blockIdx.x;
    int b   = blk >> 5;
    int n0  = (blk & 31) * 8;

    __shared__ float xs[9][DD];
    for (int t = threadIdx.x; t < 9 * DD; t += 256) {
        int r = t / DD, d = t % DD;
        int n = (n0 + r) & (NN - 1);
        xs[r][d] = x[((size_t)b * NN + n) * DD + d];
    }
    __syncthreads();

    int c = threadIdx.x;
    float accPi[8], accPj[8];
#pragma unroll
    for (int r = 0; r < 8; r++) { accPi[r] = 0.f; accPj[r] = 0.f; }

#pragma unroll 4
    for (int d = 0; d < DD; d++) {
        float wa = W1[(0 * DD + d) * KK + c];
        float wb = W1[(1 * DD + d) * KK + c];
        float wc = W1[(2 * DD + d) * KK + c];
        float wd = W1[(3 * DD + d) * KK + c];
#pragma unroll
        for (int r = 0; r < 8; r++) {
            float xv  = xs[r][d];
            float xnv = xs[r + 1][d];
            accPi[r] += xv * wa + xnv * wb;
            accPj[r] += xv * wc + xnv * wd;
        }
    }
    float b1c = b1[c];
#pragma unroll
    for (int r = 0; r < 8; r++) {
        int n = n0 + r;
        size_t off = ((size_t)b * NN + n) * KK + c;
        g_Pi[off] = accPi[r] + b1c;
        g_Pj[off] = accPj[r];
    }
}

// ---------------------------------------------------------------------------
// W2 prep: transpose [k][c] fp32 -> [c][k] half
// ---------------------------------------------------------------------------
__global__ void w2prep_kernel(const float* __restrict__ W2) {
    int idx = blockIdx.x * 256 + threadIdx.x;  // k*128 + c
    int k = idx >> 7, c = idx & 127;
    g_W2h[c * KK + k] = __float2half_rn(W2[idx]);
}

// ---------------------------------------------------------------------------
// Pair kernel: CTA = (b, {i0,i0+1}, j-tile of 128), fp16 m16n8k16.
//   For each i: C[j,c] = sum_k relu(Pi[i,k]+Pj[j,k]) * W2[k,c]  (128x128x256)
//   score = tanh( sum_c relu(C + b2) * W3 + b3 ), masked.
// 256 thr = 8 warps: wy=wid&3 -> j 32-range, wx=wid>>2 -> c 64-range.
// W2 (half, [c][k] padded stride 264) fully SMEM-resident.
// A = half(relu(Pi+Pj)) staged per K=16 chunk, double buffered.
// ---------------------------------------------------------------------------
#define BROW 264                       // B smem row stride (halves): 256+8
#define AROW 24                        // A smem row stride (halves): 16+8

// byte offsets in dynamic smem
#define OFF_BH   0                     // 128*264*2      = 67584
#define OFF_AH   67584                 // 2*2*128*24*2   = 24576
#define OFF_PI   92160                 // 2*256*4        = 2048
#define OFF_B2   94208                 // 512
#define OFF_W3   94720                 // 512
#define OFF_RED  95232                 // 2*128*2*4      = 2048
#define SMEM_BYTES 97280

__global__ __launch_bounds__(256) void pair_kernel(const float* __restrict__ b2g,
                                                   const float* __restrict__ w3g,
                                                   const float* __restrict__ b3g,
                                                   float* __restrict__ outm) {
    extern __shared__ char smem[];
    __half* Bh  = (__half*)(smem + OFF_BH);
    __half* Ah  = (__half*)(smem + OFF_AH);
    float*  PiS = (float*)(smem + OFF_PI);
    float*  b2s = (float*)(smem + OFF_B2);
    float*  w3s = (float*)(smem + OFF_W3);
    float*  red = (float*)(smem + OFF_RED);

    int tid  = threadIdx.x;
    int lane = tid & 31, wid = tid >> 5;
    int wy = wid & 3, wx = wid >> 2;
    int g  = lane >> 2, tg = lane & 3;

    int bid = blockIdx.x;
    int jt = bid & 1;
    int ig = (bid >> 1) & 127;
    int b  = bid >> 8;
    int j0 = jt << 7, i0 = ig << 1;
    if (i0 > j0 + 125) return;         // fully masked tile (output zeroed by memset)

    const float* Pjb = &g_Pj[(size_t)(b * NN + j0) * KK];

    // Prologue: W2 half image (4096 uint4), Pi rows, b2, W3
    {
        const uint4* wsrc = (const uint4*)g_W2h;
#pragma unroll
        for (int q = tid; q < 128 * 32; q += 256) {
            int cc = q >> 5, qq = q & 31;
            *(uint4*)&Bh[cc * BROW + qq * 8] = wsrc[cc * 32 + qq];
        }
        const float* pi0 = &g_Pi[(size_t)(b * NN + i0) * KK];
        PiS[tid]       = pi0[tid];
        PiS[256 + tid] = pi0[KK + tid];
        if (tid < 128) { b2s[tid] = b2g[tid]; w3s[tid] = w3g[tid]; }
    }

    float acc[2][2][8][4];
#pragma unroll
    for (int i = 0; i < 2; i++)
#pragma unroll
        for (int m = 0; m < 2; m++)
#pragma unroll
            for (int n = 0; n < 8; n++)
#pragma unroll
                for (int q = 0; q < 4; q++) acc[i][m][n][q] = 0.f;

    // A staging mapping: thread -> (row jA, k-range kq..kq+7)
    int jA = tid >> 1, kq = (tid & 1) * 8;

    // Load chunk 0 Pj into regs
    float4 pj0 = *(const float4*)&Pjb[(size_t)jA * KK + kq];
    float4 pj1 = *(const float4*)&Pjb[(size_t)jA * KK + kq + 4];

    __syncthreads();   // PiS (and Bh) ready

    // Store chunk 0 into buf 0
#pragma unroll
    for (int i = 0; i < 2; i++) {
        const float* pb = &PiS[i * 256 + kq];
        __half2 h0 = __floats2half2_rn(fmaxf(pj0.x + pb[0], 0.f), fmaxf(pj0.y + pb[1], 0.f));
        __half2 h1 = __floats2half2_rn(fmaxf(pj0.z + pb[2], 0.f), fmaxf(pj0.w + pb[3], 0.f));
        __half2 h2 = __floats2half2_rn(fmaxf(pj1.x + pb[4], 0.f), fmaxf(pj1.y + pb[5], 0.f));
        __half2 h3 = __floats2half2_rn(fmaxf(pj1.z + pb[6], 0.f), fmaxf(pj1.w + pb[7], 0.f));
        uint4 v;
        v.x = h2_as_u32(h0); v.y = h2_as_u32(h1);
        v.z = h2_as_u32(h2); v.w = h2_as_u32(h3);
        *(uint4*)&Ah[(i * 128 + jA) * AROW + kq] = v;
    }
    __syncthreads();

    for (int c = 0; c < 16; c++) {
        int buf = c & 1;
        int k0 = c << 4;
        // Prefetch next Pj chunk
        if (c < 15) {
            int kn = k0 + 16;
            pj0 = *(const float4*)&Pjb[(size_t)jA * KK + kn + kq];
            pj1 = *(const float4*)&Pjb[(size_t)jA * KK + kn + kq + 4];
        }

        // Compute chunk c
        {
            const __half* Ab = Ah + (size_t)buf * 2 * 128 * AROW;
            uint32_t bf0[8], bf1[8];
#pragma unroll
            for (int n = 0; n < 8; n++) {
                int cc = wx * 64 + n * 8 + g;
                const __half* bp = &Bh[cc * BROW + k0 + 2 * tg];
                bf0[n] = *(const uint32_t*)bp;
                bf1[n] = *(const uint32_t*)(bp + 8);
            }
#pragma unroll
            for (int i = 0; i < 2; i++) {
#pragma unroll
                for (int m = 0; m < 2; m++) {
                    int row = wy * 32 + m * 16 + g;
                    const __half* ap = Ab + (i * 128 + row) * AROW + 2 * tg;
                    uint32_t a0 = *(const uint32_t*)ap;
                    uint32_t a1 = *(const uint32_t*)(ap + 8 * AROW);
                    uint32_t a2 = *(const uint32_t*)(ap + 8);
                    uint32_t a3 = *(const uint32_t*)(ap + 8 * AROW + 8);
#pragma unroll
                    for (int n = 0; n < 8; n++)
                        mma_f16(acc[i][m][n], a0, a1, a2, a3, bf0[n], bf1[n]);
                }
            }
        }

        // Store chunk c+1 into the other buffer
        if (c < 15) {
            int nb = buf ^ 1;
#pragma unroll
            for (int i = 0; i < 2; i++) {
                const float* pb = &PiS[i * 256 + k0 + 16 + kq];
                __half2 h0 = __floats2half2_rn(fmaxf(pj0.x + pb[0], 0.f), fmaxf(pj0.y + pb[1], 0.f));
                __half2 h1 = __floats2half2_rn(fmaxf(pj0.z + pb[2], 0.f), fmaxf(pj0.w + pb[3], 0.f));
                __half2 h2 = __floats2half2_rn(fmaxf(pj1.x + pb[4], 0.f), fmaxf(pj1.y + pb[5], 0.f));
                __half2 h3 = __floats2half2_rn(fmaxf(pj1.z + pb[6], 0.f), fmaxf(pj1.w + pb[7], 0.f));
                uint4 v;
                v.x = h2_as_u32(h0); v.y = h2_as_u32(h1);
                v.z = h2_as_u32(h2); v.w = h2_as_u32(h3);
                *(uint4*)&Ah[((nb * 2 + i) * 128 + jA) * AROW + kq] = v;
            }
        }
        __syncthreads();
    }

    // Epilogue: relu(C+b2).W3 partial dots, shfl + smem reduce, tanh, mask, store
    float b3v = b3g[0];
#pragma unroll
    for (int i = 0; i < 2; i++) {
#pragma unroll
        for (int m = 0; m < 2; m++) {
            float s0 = 0.f, s1 = 0.f;
#pragma unroll
            for (int n = 0; n < 8; n++) {
                int c0 = wx * 64 + n * 8 + tg * 2;
                float bA = b2s[c0],      wA = w3s[c0];
                float bBv = b2s[c0 + 1], wBv = w3s[c0 + 1];
                s0 += fmaxf(acc[i][m][n][0] + bA, 0.f) * wA
                    + fmaxf(acc[i][m][n][1] + bBv, 0.f) * wBv;
                s1 += fmaxf(acc[i][m][n][2] + bA, 0.f) * wA
                    + fmaxf(acc[i][m][n][3] + bBv, 0.f) * wBv;
            }
            s0 += __shfl_xor_sync(0xffffffffu, s0, 1);
            s0 += __shfl_xor_sync(0xffffffffu, s0, 2);
            s1 += __shfl_xor_sync(0xffffffffu, s1, 1);
            s1 += __shfl_xor_sync(0xffffffffu, s1, 2);
            if (tg == 0) {
                int r0 = wy * 32 + m * 16 + g;
                red[(i * 128 + r0) * 2 + wx]     = s0;
                red[(i * 128 + r0 + 8) * 2 + wx] = s1;
            }
        }
    }
    __syncthreads();

    {
        int i  = tid >> 7;
        int jj = tid & 127;
        float sum = red[(i * 128 + jj) * 2] + red[(i * 128 + jj) * 2 + 1] + b3v;
        int iG = i0 + i, j = j0 + jj;
        bool valid = (j >= iG + 2) && ((j - iG) != (NN - 1));
        outm[((size_t)(b * NN + iG)) * NN + j] = valid ? tanhf(sum) : 0.f;
    }
}

// ---------------------------------------------------------------------------
// Launcher
// ---------------------------------------------------------------------------
extern "C" void kernel_launch(void* const* d_in, const int* in_sizes, int n_in,
                              void* d_out, int out_size) {
    const float* x  = (const float*)d_in[0];
    const float* W1 = (const float*)d_in[1];
    const float* b1 = (const float*)d_in[2];
    const float* W2 = (const float*)d_in[3];
    const float* b2 = (const float*)d_in[4];
    const float* W3 = (const float*)d_in[5];
    const float* b3 = (const float*)d_in[6];
    float* out = (float*)d_out;

    const int MAT  = BB * NN * NN;   // 524288
    const int TOUR = BB * NN;        // 2048

    size_t matOff = 0;
    bool hasTour = false;
    if (out_size >= MAT + TOUR) { hasTour = true; matOff = (size_t)out_size - MAT; }

    cudaFuncSetAttribute(pair_kernel, cudaFuncAttributeMaxDynamicSharedMemorySize,
                         SMEM_BYTES);

    cudaMemsetAsync(d_out, 0, (size_t)out_size * sizeof(float), 0);
    if (hasTour) tour_kernel<<<(TOUR + 255) / 256, 256>>>(out);

    proj_kernel<<<256, 256>>>(x, W1, b1);
    w2prep_kernel<<<128, 256>>>(W2);
    pair_kernel<<<BB * 128 * 2, 256, SMEM_BYTES>>>(b2, W3, b3, out + matOff);
}